// round 14
// baseline (speedup 1.0000x reference)
#include <cuda_runtime.h>
#include <cuda_bf16.h>

#define FULL 0xffffffffu

static constexpr int B = 64;
static constexpr int S = 512;
static constexpr int H = 768;
static constexpr int L = 9;
static constexpr int VROW = 12;       // floats per vbuf row
static constexpr int NCHUNK = 32;     // 16-timestep chunks
static constexpr int CHUNK_TGT = 32;  // emis blocks per chunk

__device__ float g_em[B * S * L];     // [b][t][j]
__device__ float g_score[B];
__device__ float g_logZ[B];
__device__ float g_corr[B];
__device__ int   g_cnt[NCHUNK];       // per-chunk production counters
__device__ unsigned g_done;           // finished crf blocks (target 128)

// smem overlay offsets (crf blocks) / sWT (emis blocks)
static constexpr int SM_VBUF = 0;                       // 24528 B
static constexpr int SM_BP   = 24528;                   // 4599 B
static constexpr int SM_COMP = 29127;                   // 2295 B
static constexpr int SM_ETAG = 31424;                   // 256 B (aligned)
static constexpr int SM_PROG = 31680;                   // 4 B
static constexpr int SM_SIZE = 31688;

__device__ __forceinline__ void spin_ready(int& ready, int need) {
    while (ready < need) {
        if (*(volatile int*)&g_cnt[ready] == CHUNK_TGT) { ready++; __threadfence(); }
        else __nanosleep(128);
    }
}

// ---------------------------------------------------------------------------
// Fused kernel: 128 crf blocks + 1024 emis blocks (t-major), 256 threads.
// ---------------------------------------------------------------------------
__global__ void __launch_bounds__(256)
fused_kernel(const float* __restrict__ hidden,
             const int* __restrict__ label,
             const int* __restrict__ mask,
             const float* __restrict__ W,
             const float* __restrict__ bias,
             const float* __restrict__ startT,
             const float* __restrict__ endT,
             const float* __restrict__ trans,
             float* __restrict__ out) {
    __shared__ __align__(16) char smr[SM_SIZE];

    int bid = blockIdx.x;
    int tid = threadIdx.x;

    if (bid >= 128) {
        // ================= emissions producer (t-major) =================
        float* sWT = (float*)smr;                 // [j][h], 27648 B
        for (int i = tid; i < L * H; i += 256) {
            int j = i / H, h = i - j * H;
            sWT[i] = W[h * L + j];
        }
        __syncthreads();

        int e = bid - 128;
        int tc = e >> 5;          // chunk 0..31
        int pair = e & 31;        // batch pair
        int warp = tid >> 5;
        int lane = tid & 31;
        int b = 2 * pair + (warp >> 2);
        int t0 = tc * 16 + (warp & 3) * 4;
        long row0 = (long)b * S + t0;             // multiple of 4
        const float* h0 = hidden + row0 * H;

        float acc[4][9];
#pragma unroll
        for (int r = 0; r < 4; r++)
#pragma unroll
            for (int j = 0; j < 9; j++) acc[r][j] = 0.f;

#pragma unroll
        for (int k = 0; k < 6; k++) {
            int hb = k * 128 + lane * 4;
            float4 x0 = *(const float4*)(h0 + hb);
            float4 x1 = *(const float4*)(h0 + H + hb);
            float4 x2 = *(const float4*)(h0 + 2 * H + hb);
            float4 x3 = *(const float4*)(h0 + 3 * H + hb);
#pragma unroll
            for (int j = 0; j < 9; j++) {
                float4 w4 = *(const float4*)(sWT + j * H + hb);
                acc[0][j] = fmaf(x0.x, w4.x, acc[0][j]);
                acc[0][j] = fmaf(x0.y, w4.y, acc[0][j]);
                acc[0][j] = fmaf(x0.z, w4.z, acc[0][j]);
                acc[0][j] = fmaf(x0.w, w4.w, acc[0][j]);
                acc[1][j] = fmaf(x1.x, w4.x, acc[1][j]);
                acc[1][j] = fmaf(x1.y, w4.y, acc[1][j]);
                acc[1][j] = fmaf(x1.z, w4.z, acc[1][j]);
                acc[1][j] = fmaf(x1.w, w4.w, acc[1][j]);
                acc[2][j] = fmaf(x2.x, w4.x, acc[2][j]);
                acc[2][j] = fmaf(x2.y, w4.y, acc[2][j]);
                acc[2][j] = fmaf(x2.z, w4.z, acc[2][j]);
                acc[2][j] = fmaf(x2.w, w4.w, acc[2][j]);
                acc[3][j] = fmaf(x3.x, w4.x, acc[3][j]);
                acc[3][j] = fmaf(x3.y, w4.y, acc[3][j]);
                acc[3][j] = fmaf(x3.z, w4.z, acc[3][j]);
                acc[3][j] = fmaf(x3.w, w4.w, acc[3][j]);
            }
        }

#pragma unroll
        for (int r = 0; r < 4; r++)
#pragma unroll
            for (int j = 0; j < 9; j++) {
#pragma unroll
                for (int o = 16; o > 0; o >>= 1)
                    acc[r][j] += __shfl_xor_sync(FULL, acc[r][j], o);
            }

        if (lane == 0) {
            float v[36];
#pragma unroll
            for (int r = 0; r < 4; r++)
#pragma unroll
                for (int j = 0; j < 9; j++) v[r * 9 + j] = acc[r][j] + bias[j];
            float4* dst = (float4*)(g_em + row0 * 9);
#pragma unroll
            for (int q = 0; q < 9; q++)
                dst[q] = make_float4(v[4 * q], v[4 * q + 1], v[4 * q + 2], v[4 * q + 3]);
        }
        __syncthreads();
        if (tid == 0) { __threadfence(); atomicAdd(&g_cnt[tc], 1); }
        return;
    }

    // ======================= crf blocks (bid < 128) =======================
    int warp = tid >> 5;
    if (warp >= 2) return;
    int lane = tid & 31;
    int jj = lane % 9;
    int gg = (lane / 9) % 3;
    int g3 = gg * 3;
    int peer1 = jj + 9 * ((gg + 1) % 3);
    int peer2 = jj + 9 * ((gg + 2) % 3);

    float* vbuf = (float*)(smr + SM_VBUF);
    unsigned char* bp = (unsigned char*)(smr + SM_BP);
    unsigned char* comp = (unsigned char*)(smr + SM_COMP);
    unsigned char* etag = (unsigned char*)(smr + SM_ETAG);
    int* prog = (int*)(smr + SM_PROG);

    if (tid == 0) *prog = 0;
    asm volatile("bar.sync 1, 64;" ::: "memory");   // barrier #1 (warps 0,1)

    if (bid < 64) {
        int b = bid;
        const float* emb = g_em + (long)b * S * L;

        if (warp == 0) {
            // ===== Viterbi value chain (R13 math, __ldcg loads, probe sync) =====
            float T0 = trans[(g3 + 0) * 9 + jj];
            float T1 = trans[(g3 + 1) * 9 + jj];
            float T2 = trans[(g3 + 2) * 9 + jj];

            int ready = 0;
            spin_ready(ready, 1);
            int pend = (ready < NCHUNK) ? __ldcg(&g_cnt[ready]) : CHUNK_TGT;

            float v = startT[jj] + __ldcg(emb + jj);
            float cur[8];
#pragma unroll
            for (int k = 0; k < 8; k++) cur[k] = __ldcg(emb + (1 + k) * 9 + jj);

            int tb = 1;
            for (; tb + 8 <= S; tb += 8) {
                // pipelined readiness: consume old probe, spin only if behind
                if (pend == CHUNK_TGT && ready < NCHUNK) { ready++; __threadfence(); }
                int need = ((tb + 15) >> 4) + 1;
                if (need > NCHUNK) need = NCHUNK;
                if (ready < need) spin_ready(ready, need);
                pend = (ready < NCHUNK) ? __ldcg(&g_cnt[ready]) : CHUNK_TGT;

                float nxt[8];
#pragma unroll
                for (int k = 0; k < 8; k++) {
                    int t2 = tb + 8 + k;
                    nxt[k] = (t2 < S) ? __ldcg(emb + t2 * 9 + jj) : 0.f;
                }
#pragma unroll
                for (int k = 0; k < 8; k++) {
                    int t = tb + k;
                    float e = cur[k];
                    if (lane < 9) vbuf[(t - 1) * VROW + jj] = v;  // off-chain store
                    float r0 = __shfl_sync(FULL, v, g3);
                    float r1 = __shfl_sync(FULL, v, g3 + 1);
                    float r2 = __shfl_sync(FULL, v, g3 + 2);
                    float u0 = r0 + T0;
                    float u1 = r1 + T1;
                    float u2 = r2 + T2;
                    float pm = fmaxf(fmaxf(u0, u1), u2);
                    float q1 = __shfl_sync(FULL, pm, peer1);
                    float q2 = __shfl_sync(FULL, pm, peer2);
                    float U = fmaxf(pm, fmaxf(q1, q2));   // max exact in any order
                    v = U + e;   // rounding-monotone hoist of +e
                }
#pragma unroll
                for (int k = 0; k < 8; k++) cur[k] = nxt[k];
                __syncwarp();
                if (lane == 0) { __threadfence_block(); *(volatile int*)prog = tb + 7; }
            }
#pragma unroll
            for (int k = 0; k < 7; k++) {                 // t = 505..511
                int t = tb + k;
                float e = cur[k];
                if (lane < 9) vbuf[(t - 1) * VROW + jj] = v;
                float r0 = __shfl_sync(FULL, v, g3);
                float r1 = __shfl_sync(FULL, v, g3 + 1);
                float r2 = __shfl_sync(FULL, v, g3 + 2);
                float u0 = r0 + T0;
                float u1 = r1 + T1;
                float u2 = r2 + T2;
                float pm = fmaxf(fmaxf(u0, u1), u2);
                float q1 = __shfl_sync(FULL, pm, peer1);
                float q2 = __shfl_sync(FULL, pm, peer2);
                float U = fmaxf(pm, fmaxf(q1, q2));
                v = U + e;
            }
            __syncwarp();
            if (lane == 0) { __threadfence_block(); *(volatile int*)prog = S - 1; }
            __syncwarp();

            float fj = v + endT[jj];
            float fv[9];
#pragma unroll
            for (int i = 0; i < 9; i++) fv[i] = __shfl_sync(FULL, fj, i);
            float best = fv[0];
            int tag511 = 0;
#pragma unroll
            for (int i = 1; i < 9; i++)
                if (fv[i] > best) { best = fv[i]; tag511 = i; }   // first-max tie

            asm volatile("bar.sync 1, 64;" ::: "memory");   // barrier #2: join bp

            for (int idx = lane; idx < 255 * 9; idx += 32) {
                int ci = idx / 9;
                int j = idx - ci * 9;
                int t = 2 * ci + 2;
                comp[idx] = bp[(t - 2) * 9 + bp[(t - 1) * 9 + j]];
            }
            __syncwarp();

            if (lane == 0) {
                int cur_t = bp[510 * 9 + tag511];   // tag at t=510
                etag[255] = (unsigned char)cur_t;
                for (int t = 510; t >= 2; t -= 2) {
                    cur_t = comp[((t - 2) >> 1) * 9 + cur_t];
                    etag[(t - 2) >> 1] = (unsigned char)cur_t;
                }
            }
            __syncwarp();

            const int* lb = label + b * S;
            float* pout = out + 2 + (long)b * S;
            float cnt = 0.f;
            for (int t = lane; t < S; t += 32) {
                int tg;
                if (t == 511) tg = tag511;
                else if ((t & 1) == 0) tg = etag[t >> 1];
                else tg = bp[t * 9 + etag[(t + 1) >> 1]];
                int lab = lb[t];
                int pv = (lab > 0) ? tg : 0;
                pout[t] = (float)pv;
                cnt += (pv == lab) ? 1.f : 0.f;
            }
#pragma unroll
            for (int o = 16; o > 0; o >>= 1) cnt += __shfl_xor_sync(FULL, cnt, o);
            if (lane == 0) g_corr[b] = cnt;

        } else {
            // ===== trailing bp/argmax pass (reference op order) =====
            float Tc[9];
#pragma unroll
            for (int i = 0; i < 9; i++) Tc[i] = trans[i * 9 + jj];
            int g = lane / 9;
            bool act = (lane < 27);

            for (int tc2 = 1; tc2 <= S - 1; tc2 += 3) {
                int t = tc2 + g;
                int need = tc2 + 2 < S - 1 ? tc2 + 2 : S - 1;
                while (*(volatile int*)prog < need) __nanosleep(64);
                if (act && t <= S - 1) {
                    const float* vb = &vbuf[(t - 1) * VROW];
                    float4 a0 = *(const float4*)(vb);
                    float4 a1 = *(const float4*)(vb + 4);
                    float v8 = vb[8];
                    float e = __ldcg(emb + t * 9 + jj);
                    float vi[9];
                    vi[0] = (a0.x + Tc[0]) + e;
                    vi[1] = (a0.y + Tc[1]) + e;
                    vi[2] = (a0.z + Tc[2]) + e;
                    vi[3] = (a0.w + Tc[3]) + e;
                    vi[4] = (a1.x + Tc[4]) + e;
                    vi[5] = (a1.y + Tc[5]) + e;
                    vi[6] = (a1.z + Tc[6]) + e;
                    vi[7] = (a1.w + Tc[7]) + e;
                    vi[8] = (v8 + Tc[8]) + e;
                    float a01 = fmaxf(vi[0], vi[1]);
                    float a23 = fmaxf(vi[2], vi[3]);
                    float a45 = fmaxf(vi[4], vi[5]);
                    float a67 = fmaxf(vi[6], vi[7]);
                    float M = fmaxf(fmaxf(fmaxf(a01, a23), fmaxf(a45, a67)), vi[8]);
                    int arg = 8;                  // first-occurrence
#pragma unroll
                    for (int i = 7; i >= 0; i--) arg = (vi[i] == M) ? i : arg;
                    bp[(t - 1) * 9 + jj] = (unsigned char)arg;
                }
            }
            asm volatile("bar.sync 1, 64;" ::: "memory");   // barrier #2
            return;
        }

    } else {
        if (warp == 1) return;      // fwd blocks need no second warp
        // ---------- forward DP (logZ), 3-way split, then numerator ----------
        int b = bid - 64;
        const float* emb = g_em + (long)b * S * L;
        const int* mb = mask + b * S;
        float E0 = __expf(trans[(g3 + 0) * 9 + jj]);
        float E1 = __expf(trans[(g3 + 1) * 9 + jj]);
        float E2 = __expf(trans[(g3 + 2) * 9 + jj]);
        float eend = __expf(endT[jj]);

        int ready = 0;
        spin_ready(ready, 1);
        int pend = (ready < NCHUNK) ? __ldcg(&g_cnt[ready]) : CHUNK_TGT;

        float p = __expf(startT[jj] + __ldcg(emb + jj));
        float logacc = 0.f;

        float cur[8]; int mcur[8];
#pragma unroll
        for (int k = 0; k < 8; k++) { cur[k] = __ldcg(emb + (1 + k) * 9 + jj); mcur[k] = mb[1 + k]; }

        int tb = 1;
        for (; tb + 8 <= S; tb += 8) {
            if (pend == CHUNK_TGT && ready < NCHUNK) { ready++; __threadfence(); }
            int need = ((tb + 15) >> 4) + 1;
            if (need > NCHUNK) need = NCHUNK;
            if (ready < need) spin_ready(ready, need);
            pend = (ready < NCHUNK) ? __ldcg(&g_cnt[ready]) : CHUNK_TGT;

            float w[8];
#pragma unroll
            for (int k = 0; k < 8; k++) w[k] = __expf(cur[k]);
            float nxt[8]; int mnxt[8];
#pragma unroll
            for (int k = 0; k < 8; k++) {
                int t2 = tb + 8 + k;
                if (t2 < S) { nxt[k] = __ldcg(emb + t2 * 9 + jj); mnxt[k] = mb[t2]; }
                else        { nxt[k] = 0.f;                       mnxt[k] = 0; }
            }
#pragma unroll
            for (int k = 0; k < 8; k++) {
                int t = tb + k;
                float r0 = __shfl_sync(FULL, p, g3);
                float r1 = __shfl_sync(FULL, p, g3 + 1);
                float r2 = __shfl_sync(FULL, p, g3 + 2);
                float sp = fmaf(r0, E0, r1 * E1);
                sp = fmaf(r2, E2, sp);
                float q1 = __shfl_sync(FULL, sp, peer1);
                float q2 = __shfl_sync(FULL, sp, peer2);
                float s = (sp + q1) + q2;
                float pn = s * w[k];
                p = (mcur[k] > 0) ? pn : p;
                if ((t & 15) == 0) {
                    float r = __shfl_sync(FULL, p, 0);
                    logacc += __logf(r);
                    p *= __fdividef(1.0f, r);
                }
            }
#pragma unroll
            for (int k = 0; k < 8; k++) { cur[k] = nxt[k]; mcur[k] = mnxt[k]; }
        }
#pragma unroll
        for (int k = 0; k < 7; k++) {     // t = 505..511
            float w = __expf(cur[k]);
            float r0 = __shfl_sync(FULL, p, g3);
            float r1 = __shfl_sync(FULL, p, g3 + 1);
            float r2 = __shfl_sync(FULL, p, g3 + 2);
            float sp = fmaf(r0, E0, r1 * E1);
            sp = fmaf(r2, E2, sp);
            float q1 = __shfl_sync(FULL, sp, peer1);
            float q2 = __shfl_sync(FULL, sp, peer2);
            float s = (sp + q1) + q2;
            float pn = s * w;
            p = (mcur[k] > 0) ? pn : p;
        }

        float f = p * eend;
        float tot = 0.f;
#pragma unroll
        for (int i = 0; i < 9; i++) tot += __shfl_sync(FULL, f, i);
        if (lane == 0) g_logZ[b] = logacc + __logf(tot);

        // ---------- gold path score (masked scan) + label copy ----------
        const int* lb = label + b * S;
        int t0 = lane * 16;

        int ll = -1;
#pragma unroll
        for (int k = 0; k < 16; k++) {
            int t = t0 + k;
            if ((t == 0) | (mb[t] > 0)) ll = t;
        }
        int inc = ll;
#pragma unroll
        for (int o = 1; o < 32; o <<= 1) {
            int vv = __shfl_up_sync(FULL, inc, o);
            if (lane >= o) inc = max(inc, vv);
        }
        int exc = __shfl_up_sync(FULL, inc, 1);
        if (lane == 0) exc = -1;
        int lastAll = __shfl_sync(FULL, inc, 31);

        float sc = 0.f;
        int prevIdx = exc;
#pragma unroll
        for (int k = 0; k < 16; k++) {
            int t = t0 + k;
            int mt = mb[t];
            int tg = lb[t];
            if (t >= 1) {
                int pt = lb[prevIdx];
                float s = trans[pt * 9 + tg] + __ldcg(emb + t * 9 + tg);
                sc += s * (float)mt;
            }
            if ((t == 0) | (mt > 0)) prevIdx = t;
        }
#pragma unroll
        for (int o = 16; o > 0; o >>= 1) sc += __shfl_xor_sync(FULL, sc, o);

        if (lane == 0) {
            int tg0 = lb[0];
            g_score[b] = startT[tg0] + __ldcg(emb + tg0) + sc + endT[lb[lastAll]];
        }

        float* lout = out + 2 + (long)B * S;
        for (int t = lane; t < S; t += 32)
            lout[(long)b * S + t] = (float)lb[t];
    }

    // ---------- per-block done accounting (warp0 only); last finalizes ----------
    __threadfence();
    unsigned my = 0;
    if (lane == 0) my = atomicAdd(&g_done, 1u);
    my = __shfl_sync(FULL, my, 0);
    if (my == 127u) {
        float d = 0.f, c = 0.f;
#pragma unroll
        for (int k = lane; k < 64; k += 32) {
            d += __ldcg(&g_score[k]) - __ldcg(&g_logZ[k]);
            c += __ldcg(&g_corr[k]);
        }
#pragma unroll
        for (int o = 16; o > 0; o >>= 1) {
            d += __shfl_xor_sync(FULL, d, o);
            c += __shfl_xor_sync(FULL, c, o);
        }
        if (lane == 0) {
            out[0] = -d / (float)B;
            out[1] = c;
            g_done = 0;   // reset for next graph replay
        }
        g_cnt[lane] = 0;  // lanes 0..31 reset all chunk counters
    }
}

// ---------------------------------------------------------------------------
extern "C" void kernel_launch(void* const* d_in, const int* in_sizes, int n_in,
                              void* d_out, int out_size) {
    const float* hidden = (const float*)d_in[0];
    const int*   label  = (const int*)d_in[1];
    const int*   mask   = (const int*)d_in[2];
    const float* W      = (const float*)d_in[3];
    const float* bias   = (const float*)d_in[4];
    const float* startT = (const float*)d_in[5];
    const float* endT   = (const float*)d_in[6];
    const float* trans  = (const float*)d_in[7];
    float* out = (float*)d_out;

    fused_kernel<<<128 + 1024, 256>>>(hidden, label, mask, W, bias,
                                      startT, endT, trans, out);
}

// round 15
// speedup vs baseline: 1.0758x; 1.0758x over previous
#include <cuda_runtime.h>
#include <cuda_bf16.h>

#define FULL 0xffffffffu

static constexpr int B = 64;
static constexpr int S = 512;
static constexpr int H = 768;
static constexpr int L = 9;
static constexpr int VROW = 12;       // floats per vbuf row
static constexpr int NCHUNK = 32;     // 16-timestep chunks
static constexpr int CHUNK_TGT = 32;  // emis items per chunk
static constexpr int NITEM = 1024;    // total emis work items
static constexpr int NWORK = 448;     // worker blocks launched

__device__ float g_em[B * S * L];     // [b][t][j]
__device__ float g_score[B];
__device__ float g_logZ[B];
__device__ float g_corr[B];
__device__ int   g_cnt[NCHUNK];       // per-chunk production counters
__device__ int   g_work;              // work queue cursor
__device__ unsigned g_done;           // finished chain warps (target 192)
__device__ unsigned g_wdone;          // retired workers (target NWORK)
__device__ int   g_chain_reg;         // chains registered (target 64)
__device__ unsigned char g_chain_sm[256];

// smem overlay offsets
static constexpr int SM_VBUF = 0;                       // 24528 B (48B rows, 16B aligned)
static constexpr int SM_BP   = 24528;                   // 4599 B
static constexpr int SM_COMP = 29127;                   // 2295 B
static constexpr int SM_ETAG = 31424;                   // 256 B
static constexpr int SM_PROG = 31680;                   // 4 B
static constexpr int SM_ITEM = 31684;                   // 4 B (worker queue slot)
static constexpr int SM_SIZE = 31688;

__device__ __forceinline__ void spin_ready(int& ready, int need) {
    while (ready < need) {
        if (*(volatile int*)&g_cnt[ready] == CHUNK_TGT) { ready++; __threadfence(); }
        else __nanosleep(128);
    }
}

// ---------------------------------------------------------------------------
// Fused kernel: 64 chain blocks + NWORK persistent emis workers, 256 threads.
// ---------------------------------------------------------------------------
__global__ void __launch_bounds__(256)
fused_kernel(const float* __restrict__ hidden,
             const int* __restrict__ label,
             const int* __restrict__ mask,
             const float* __restrict__ W,
             const float* __restrict__ bias,
             const float* __restrict__ startT,
             const float* __restrict__ endT,
             const float* __restrict__ trans,
             float* __restrict__ out) {
    __shared__ __align__(16) char smr[SM_SIZE];

    int bid = blockIdx.x;
    int tid = threadIdx.x;

    if (bid >= 64) {
        // ================= persistent emis worker =================
        if (tid == 0) {
            while (*(volatile int*)&g_chain_reg < 64) __nanosleep(64);
        }
        __syncthreads();
        unsigned smid;
        asm("mov.u32 %0, %%smid;" : "=r"(smid));
        if (*(volatile unsigned char*)&g_chain_sm[smid & 255]) {
            __syncthreads();
            if (tid == 0) atomicAdd(&g_wdone, 1u);
            return;   // this SM hosts a chain block: stay off it
        }

        float* sWT = (float*)smr;                 // [j][h], 27648 B
        int* sh_item = (int*)(smr + SM_ITEM);
        for (int i = tid; i < L * H; i += 256) {
            int j = i / H, h = i - j * H;
            sWT[i] = W[h * L + j];
        }
        __syncthreads();

        int warp = tid >> 5;
        int lane = tid & 31;

        for (;;) {
            if (tid == 0) *sh_item = atomicAdd(&g_work, 1);
            __syncthreads();
            int item = *sh_item;
            __syncthreads();
            if (item >= NITEM) break;

            int tc = item >> 5;       // chunk-major: chunk 0 first
            int pair = item & 31;
            int b = 2 * pair + (warp >> 2);
            int t0 = tc * 16 + (warp & 3) * 4;
            long row0 = (long)b * S + t0;         // multiple of 4
            const float* h0 = hidden + row0 * H;

            float acc[4][9];
#pragma unroll
            for (int r = 0; r < 4; r++)
#pragma unroll
                for (int j = 0; j < 9; j++) acc[r][j] = 0.f;

#pragma unroll
            for (int k = 0; k < 6; k++) {
                int hb = k * 128 + lane * 4;
                float4 x0 = *(const float4*)(h0 + hb);
                float4 x1 = *(const float4*)(h0 + H + hb);
                float4 x2 = *(const float4*)(h0 + 2 * H + hb);
                float4 x3 = *(const float4*)(h0 + 3 * H + hb);
#pragma unroll
                for (int j = 0; j < 9; j++) {
                    float4 w4 = *(const float4*)(sWT + j * H + hb);
                    acc[0][j] = fmaf(x0.x, w4.x, acc[0][j]);
                    acc[0][j] = fmaf(x0.y, w4.y, acc[0][j]);
                    acc[0][j] = fmaf(x0.z, w4.z, acc[0][j]);
                    acc[0][j] = fmaf(x0.w, w4.w, acc[0][j]);
                    acc[1][j] = fmaf(x1.x, w4.x, acc[1][j]);
                    acc[1][j] = fmaf(x1.y, w4.y, acc[1][j]);
                    acc[1][j] = fmaf(x1.z, w4.z, acc[1][j]);
                    acc[1][j] = fmaf(x1.w, w4.w, acc[1][j]);
                    acc[2][j] = fmaf(x2.x, w4.x, acc[2][j]);
                    acc[2][j] = fmaf(x2.y, w4.y, acc[2][j]);
                    acc[2][j] = fmaf(x2.z, w4.z, acc[2][j]);
                    acc[2][j] = fmaf(x2.w, w4.w, acc[2][j]);
                    acc[3][j] = fmaf(x3.x, w4.x, acc[3][j]);
                    acc[3][j] = fmaf(x3.y, w4.y, acc[3][j]);
                    acc[3][j] = fmaf(x3.z, w4.z, acc[3][j]);
                    acc[3][j] = fmaf(x3.w, w4.w, acc[3][j]);
                }
            }

#pragma unroll
            for (int r = 0; r < 4; r++)
#pragma unroll
                for (int j = 0; j < 9; j++) {
#pragma unroll
                    for (int o = 16; o > 0; o >>= 1)
                        acc[r][j] += __shfl_xor_sync(FULL, acc[r][j], o);
                }

            if (lane == 0) {
                float v[36];
#pragma unroll
                for (int r = 0; r < 4; r++)
#pragma unroll
                    for (int j = 0; j < 9; j++) v[r * 9 + j] = acc[r][j] + bias[j];
                float4* dst = (float4*)(g_em + row0 * 9);
#pragma unroll
                for (int q = 0; q < 9; q++)
                    dst[q] = make_float4(v[4 * q], v[4 * q + 1], v[4 * q + 2], v[4 * q + 3]);
            }
            __syncthreads();
            if (tid == 0) { __threadfence(); atomicAdd(&g_cnt[tc], 1); }
        }
        if (tid == 0) atomicAdd(&g_wdone, 1u);
        return;
    }

    // ======================= chain blocks (bid < 64) =======================
    int warp = tid >> 5;
    if (warp >= 4) return;
    int lane = tid & 31;
    int jj = lane % 9;
    int gg = (lane / 9) % 3;
    int g3 = gg * 3;
    int peer1 = jj + 9 * ((gg + 1) % 3);
    int peer2 = jj + 9 * ((gg + 2) % 3);

    float* vbuf = (float*)(smr + SM_VBUF);
    unsigned char* bp = (unsigned char*)(smr + SM_BP);
    unsigned char* comp = (unsigned char*)(smr + SM_COMP);
    unsigned char* etag = (unsigned char*)(smr + SM_ETAG);
    int* prog = (int*)(smr + SM_PROG);

    int b = bid;
    const float* emb = g_em + (long)b * S * L;

    if (tid == 0) {
        *prog = 0;
        unsigned smid;
        asm("mov.u32 %0, %%smid;" : "=r"(smid));
        g_chain_sm[smid & 255] = 1;
        __threadfence();
        atomicAdd(&g_chain_reg, 1);
    }
    if (warp < 2) asm volatile("bar.sync 1, 64;" ::: "memory");   // barrier #1

    if (warp == 0) {
        // ===== Viterbi value chain =====
        float T0 = trans[(g3 + 0) * 9 + jj];
        float T1 = trans[(g3 + 1) * 9 + jj];
        float T2 = trans[(g3 + 2) * 9 + jj];

        int ready = 0;
        spin_ready(ready, 1);
        int pend = (ready < NCHUNK) ? __ldcg(&g_cnt[ready]) : CHUNK_TGT;

        float v = startT[jj] + __ldcg(emb + jj);
        float cur[8];
#pragma unroll
        for (int k = 0; k < 8; k++) cur[k] = __ldcg(emb + (1 + k) * 9 + jj);

        int tb = 1;
        for (; tb + 8 <= S; tb += 8) {
            if (pend == CHUNK_TGT && ready < NCHUNK) { ready++; __threadfence(); }
            int need = ((tb + 15) >> 4) + 1;
            if (need > NCHUNK) need = NCHUNK;
            if (ready < need) spin_ready(ready, need);
            pend = (ready < NCHUNK) ? __ldcg(&g_cnt[ready]) : CHUNK_TGT;

            float nxt[8];
#pragma unroll
            for (int k = 0; k < 8; k++) {
                int t2 = tb + 8 + k;
                nxt[k] = (t2 < S) ? __ldcg(emb + t2 * 9 + jj) : 0.f;
            }
#pragma unroll
            for (int k = 0; k < 8; k++) {
                int t = tb + k;
                float e = cur[k];
                if (lane < 9) vbuf[(t - 1) * VROW + jj] = v;  // off-chain store
                float r0 = __shfl_sync(FULL, v, g3);
                float r1 = __shfl_sync(FULL, v, g3 + 1);
                float r2 = __shfl_sync(FULL, v, g3 + 2);
                float u0 = r0 + T0;
                float u1 = r1 + T1;
                float u2 = r2 + T2;
                float pm = fmaxf(fmaxf(u0, u1), u2);
                float q1 = __shfl_sync(FULL, pm, peer1);
                float q2 = __shfl_sync(FULL, pm, peer2);
                float U = fmaxf(pm, fmaxf(q1, q2));   // max exact in any order
                v = U + e;   // rounding-monotone hoist of +e
            }
#pragma unroll
            for (int k = 0; k < 8; k++) cur[k] = nxt[k];
            __syncwarp();
            if (lane == 0) { __threadfence_block(); *(volatile int*)prog = tb + 7; }
        }
#pragma unroll
        for (int k = 0; k < 7; k++) {                 // t = 505..511
            int t = tb + k;
            float e = cur[k];
            if (lane < 9) vbuf[(t - 1) * VROW + jj] = v;
            float r0 = __shfl_sync(FULL, v, g3);
            float r1 = __shfl_sync(FULL, v, g3 + 1);
            float r2 = __shfl_sync(FULL, v, g3 + 2);
            float u0 = r0 + T0;
            float u1 = r1 + T1;
            float u2 = r2 + T2;
            float pm = fmaxf(fmaxf(u0, u1), u2);
            float q1 = __shfl_sync(FULL, pm, peer1);
            float q2 = __shfl_sync(FULL, pm, peer2);
            float U = fmaxf(pm, fmaxf(q1, q2));
            v = U + e;
        }
        __syncwarp();
        if (lane == 0) { __threadfence_block(); *(volatile int*)prog = S - 1; }
        __syncwarp();

        float fj = v + endT[jj];
        float fv[9];
#pragma unroll
        for (int i = 0; i < 9; i++) fv[i] = __shfl_sync(FULL, fj, i);
        float best = fv[0];
        int tag511 = 0;
#pragma unroll
        for (int i = 1; i < 9; i++)
            if (fv[i] > best) { best = fv[i]; tag511 = i; }   // first-max tie

        asm volatile("bar.sync 1, 64;" ::: "memory");   // barrier #2: join bp

        for (int idx = lane; idx < 255 * 9; idx += 32) {
            int ci = idx / 9;
            int j = idx - ci * 9;
            int t = 2 * ci + 2;
            comp[idx] = bp[(t - 2) * 9 + bp[(t - 1) * 9 + j]];
        }
        __syncwarp();

        if (lane == 0) {
            int cur_t = bp[510 * 9 + tag511];   // tag at t=510
            etag[255] = (unsigned char)cur_t;
            for (int t = 510; t >= 2; t -= 2) {
                cur_t = comp[((t - 2) >> 1) * 9 + cur_t];
                etag[(t - 2) >> 1] = (unsigned char)cur_t;
            }
        }
        __syncwarp();

        const int* lb = label + b * S;
        float* pout = out + 2 + (long)b * S;
        float cnt = 0.f;
        for (int t = lane; t < S; t += 32) {
            int tg;
            if (t == 511) tg = tag511;
            else if ((t & 1) == 0) tg = etag[t >> 1];
            else tg = bp[t * 9 + etag[(t + 1) >> 1]];
            int lab = lb[t];
            int pv = (lab > 0) ? tg : 0;
            pout[t] = (float)pv;
            cnt += (pv == lab) ? 1.f : 0.f;
        }
#pragma unroll
        for (int o = 16; o > 0; o >>= 1) cnt += __shfl_xor_sync(FULL, cnt, o);
        if (lane == 0) g_corr[b] = cnt;

    } else if (warp == 1) {
        // ===== trailing bp/argmax pass (reference op order) =====
        float Tc[9];
#pragma unroll
        for (int i = 0; i < 9; i++) Tc[i] = trans[i * 9 + jj];
        int g = lane / 9;
        bool act = (lane < 27);

        for (int tc2 = 1; tc2 <= S - 1; tc2 += 3) {
            int t = tc2 + g;
            int need = tc2 + 2 < S - 1 ? tc2 + 2 : S - 1;
            while (*(volatile int*)prog < need) __nanosleep(64);
            if (act && t <= S - 1) {
                const float* vb = &vbuf[(t - 1) * VROW];
                float4 a0 = *(const float4*)(vb);
                float4 a1 = *(const float4*)(vb + 4);
                float v8 = vb[8];
                float e = __ldcg(emb + t * 9 + jj);
                float vi[9];
                vi[0] = (a0.x + Tc[0]) + e;
                vi[1] = (a0.y + Tc[1]) + e;
                vi[2] = (a0.z + Tc[2]) + e;
                vi[3] = (a0.w + Tc[3]) + e;
                vi[4] = (a1.x + Tc[4]) + e;
                vi[5] = (a1.y + Tc[5]) + e;
                vi[6] = (a1.z + Tc[6]) + e;
                vi[7] = (a1.w + Tc[7]) + e;
                vi[8] = (v8 + Tc[8]) + e;
                float a01 = fmaxf(vi[0], vi[1]);
                float a23 = fmaxf(vi[2], vi[3]);
                float a45 = fmaxf(vi[4], vi[5]);
                float a67 = fmaxf(vi[6], vi[7]);
                float M = fmaxf(fmaxf(fmaxf(a01, a23), fmaxf(a45, a67)), vi[8]);
                int arg = 8;                  // first-occurrence
#pragma unroll
                for (int i = 7; i >= 0; i--) arg = (vi[i] == M) ? i : arg;
                bp[(t - 1) * 9 + jj] = (unsigned char)arg;
            }
        }
        asm volatile("bar.sync 1, 64;" ::: "memory");   // barrier #2
        return;   // not counted in g_done

    } else if (warp == 2) {
        // ---------- forward DP (logZ), 3-way split ----------
        const int* mb = mask + b * S;
        float E0 = __expf(trans[(g3 + 0) * 9 + jj]);
        float E1 = __expf(trans[(g3 + 1) * 9 + jj]);
        float E2 = __expf(trans[(g3 + 2) * 9 + jj]);
        float eend = __expf(endT[jj]);

        int ready = 0;
        spin_ready(ready, 1);
        int pend = (ready < NCHUNK) ? __ldcg(&g_cnt[ready]) : CHUNK_TGT;

        float p = __expf(startT[jj] + __ldcg(emb + jj));
        float logacc = 0.f;

        float cur[8]; int mcur[8];
#pragma unroll
        for (int k = 0; k < 8; k++) { cur[k] = __ldcg(emb + (1 + k) * 9 + jj); mcur[k] = mb[1 + k]; }

        int tb = 1;
        for (; tb + 8 <= S; tb += 8) {
            if (pend == CHUNK_TGT && ready < NCHUNK) { ready++; __threadfence(); }
            int need = ((tb + 15) >> 4) + 1;
            if (need > NCHUNK) need = NCHUNK;
            if (ready < need) spin_ready(ready, need);
            pend = (ready < NCHUNK) ? __ldcg(&g_cnt[ready]) : CHUNK_TGT;

            float w[8];
#pragma unroll
            for (int k = 0; k < 8; k++) w[k] = __expf(cur[k]);
            float nxt[8]; int mnxt[8];
#pragma unroll
            for (int k = 0; k < 8; k++) {
                int t2 = tb + 8 + k;
                if (t2 < S) { nxt[k] = __ldcg(emb + t2 * 9 + jj); mnxt[k] = mb[t2]; }
                else        { nxt[k] = 0.f;                       mnxt[k] = 0; }
            }
#pragma unroll
            for (int k = 0; k < 8; k++) {
                int t = tb + k;
                float r0 = __shfl_sync(FULL, p, g3);
                float r1 = __shfl_sync(FULL, p, g3 + 1);
                float r2 = __shfl_sync(FULL, p, g3 + 2);
                float sp = fmaf(r0, E0, r1 * E1);
                sp = fmaf(r2, E2, sp);
                float q1 = __shfl_sync(FULL, sp, peer1);
                float q2 = __shfl_sync(FULL, sp, peer2);
                float s = (sp + q1) + q2;
                float pn = s * w[k];
                p = (mcur[k] > 0) ? pn : p;
                if ((t & 15) == 0) {
                    float r = __shfl_sync(FULL, p, 0);
                    logacc += __logf(r);
                    p *= __fdividef(1.0f, r);
                }
            }
#pragma unroll
            for (int k = 0; k < 8; k++) { cur[k] = nxt[k]; mcur[k] = mnxt[k]; }
        }
#pragma unroll
        for (int k = 0; k < 7; k++) {     // t = 505..511
            float w = __expf(cur[k]);
            float r0 = __shfl_sync(FULL, p, g3);
            float r1 = __shfl_sync(FULL, p, g3 + 1);
            float r2 = __shfl_sync(FULL, p, g3 + 2);
            float sp = fmaf(r0, E0, r1 * E1);
            sp = fmaf(r2, E2, sp);
            float q1 = __shfl_sync(FULL, sp, peer1);
            float q2 = __shfl_sync(FULL, sp, peer2);
            float s = (sp + q1) + q2;
            float pn = s * w;
            p = (mcur[k] > 0) ? pn : p;
        }

        float f = p * eend;
        float tot = 0.f;
#pragma unroll
        for (int i = 0; i < 9; i++) tot += __shfl_sync(FULL, f, i);
        if (lane == 0) g_logZ[b] = logacc + __logf(tot);

    } else {
        // ---------- numerator (gold path score) + label copy ----------
        const int* lb = label + b * S;
        const int* mb = mask + b * S;
        int t0 = lane * 16;

        int ready = 0;
        spin_ready(ready, NCHUNK);   // needs full batch

        int ll = -1;
#pragma unroll
        for (int k = 0; k < 16; k++) {
            int t = t0 + k;
            if ((t == 0) | (mb[t] > 0)) ll = t;
        }
        int inc = ll;
#pragma unroll
        for (int o = 1; o < 32; o <<= 1) {
            int vv = __shfl_up_sync(FULL, inc, o);
            if (lane >= o) inc = max(inc, vv);
        }
        int exc = __shfl_up_sync(FULL, inc, 1);
        if (lane == 0) exc = -1;
        int lastAll = __shfl_sync(FULL, inc, 31);

        float sc = 0.f;
        int prevIdx = exc;
#pragma unroll
        for (int k = 0; k < 16; k++) {
            int t = t0 + k;
            int mt = mb[t];
            int tg = lb[t];
            if (t >= 1) {
                int pt = lb[prevIdx];
                float s = trans[pt * 9 + tg] + __ldcg(emb + t * 9 + tg);
                sc += s * (float)mt;
            }
            if ((t == 0) | (mt > 0)) prevIdx = t;
        }
#pragma unroll
        for (int o = 16; o > 0; o >>= 1) sc += __shfl_xor_sync(FULL, sc, o);

        if (lane == 0) {
            int tg0 = lb[0];
            g_score[b] = startT[tg0] + __ldcg(emb + tg0) + sc + endT[lb[lastAll]];
        }

        float* lout = out + 2 + (long)B * S;
        for (int t = lane; t < S; t += 32)
            lout[(long)b * S + t] = (float)lb[t];
    }

    // ---------- done accounting (warps 0,2,3); last of 192 finalizes ----------
    __threadfence();
    unsigned my = 0;
    if (lane == 0) my = atomicAdd(&g_done, 1u);
    my = __shfl_sync(FULL, my, 0);
    if (my == 191u) {
        // wait for all workers to retire before resetting shared state
        if (lane == 0) {
            while (*(volatile unsigned*)&g_wdone < (unsigned)NWORK) __nanosleep(128);
        }
        __syncwarp();
        float d = 0.f, c = 0.f;
#pragma unroll
        for (int k = lane; k < 64; k += 32) {
            d += __ldcg(&g_score[k]) - __ldcg(&g_logZ[k]);
            c += __ldcg(&g_corr[k]);
        }
#pragma unroll
        for (int o = 16; o > 0; o >>= 1) {
            d += __shfl_xor_sync(FULL, d, o);
            c += __shfl_xor_sync(FULL, c, o);
        }
        if (lane == 0) {
            out[0] = -d / (float)B;
            out[1] = c;
        }
        // reset everything for next graph replay
        g_cnt[lane] = 0;
        for (int k = lane; k < 256; k += 32) g_chain_sm[k] = 0;
        if (lane == 0) { g_work = 0; g_chain_reg = 0; g_wdone = 0; g_done = 0; }
    }
}

// ---------------------------------------------------------------------------
extern "C" void kernel_launch(void* const* d_in, const int* in_sizes, int n_in,
                              void* d_out, int out_size) {
    const float* hidden = (const float*)d_in[0];
    const int*   label  = (const int*)d_in[1];
    const int*   mask   = (const int*)d_in[2];
    const float* W      = (const float*)d_in[3];
    const float* bias   = (const float*)d_in[4];
    const float* startT = (const float*)d_in[5];
    const float* endT   = (const float*)d_in[6];
    const float* trans  = (const float*)d_in[7];
    float* out = (float*)d_out;

    fused_kernel<<<64 + NWORK, 256>>>(hidden, label, mask, W, bias,
                                      startT, endT, trans, out);
}